// round 14
// baseline (speedup 1.0000x reference)
#include <cuda_runtime.h>
#include <cstddef>
#include <cstdint>

#define N_USERS 200000
#define N_MOVIES 80000
#define NN 280000
#define HDIM 64
#define F_MOVIE 20
#define NE 1250000
#define NEL 500000
#define NB2 274           // ceil(NN / 1024)
#define BK 72             // bf16 row stride (144 bytes) for MMA smem tiles

typedef unsigned long long u64;

// Scratch (static device globals: allowed; runtime allocation is not).
__device__ __align__(16) float g_X[(size_t)NN * HDIM];
__device__ __align__(16) float g_Y[(size_t)NN * HDIM];
__device__ __align__(16) float g_Z[(size_t)NN * HDIM];
__device__ __align__(16) float g_M[(size_t)NN * HDIM];
__device__ int g_DEGI[NN];
__device__ int g_OFF[NN + 1];
__device__ int g_CUR[NN];
__device__ int g_CSR[NE];      // holds src*HDIM (premultiplied)
__device__ int g_BSUM[512];

__device__ __forceinline__ uint32_t smem_u32(const void* p) {
    return (uint32_t)__cvta_generic_to_shared(p);
}

#define LDSM4(d, addr) \
    asm volatile("ldmatrix.sync.aligned.m8n8.x4.shared.b16 {%0,%1,%2,%3}, [%4];" \
                 : "=r"((d)[0]), "=r"((d)[1]), "=r"((d)[2]), "=r"((d)[3]) \
                 : "r"(addr))

#define MMA16816(acc, a, b0v, b1v) \
    asm volatile("mma.sync.aligned.m16n8k16.row.col.f32.bf16.bf16.f32 " \
                 "{%0,%1,%2,%3}, {%4,%5,%6,%7}, {%8,%9}, {%0,%1,%2,%3};" \
                 : "+f"((acc)[0]), "+f"((acc)[1]), "+f"((acc)[2]), "+f"((acc)[3]) \
                 : "r"((a)[0]), "r"((a)[1]), "r"((a)[2]), "r"((a)[3]), \
                   "r"(b0v), "r"(b1v))

// split x -> hi (truncated bf16) + lo (truncated bf16 of exact residual)
__device__ __forceinline__ void store_split(uint16_t* sh, uint16_t* sl,
                                            int off, float4 v) {
    uint32_t ux = __float_as_uint(v.x), uy = __float_as_uint(v.y);
    uint32_t uz = __float_as_uint(v.z), uw = __float_as_uint(v.w);
    float hx = __uint_as_float(ux & 0xFFFF0000u);
    float hy = __uint_as_float(uy & 0xFFFF0000u);
    float hz = __uint_as_float(uz & 0xFFFF0000u);
    float hw = __uint_as_float(uw & 0xFFFF0000u);
    uint32_t h01 = __byte_perm(ux, uy, 0x7632);
    uint32_t h23 = __byte_perm(uz, uw, 0x7632);
    uint32_t l01 = __byte_perm(__float_as_uint(v.x - hx),
                               __float_as_uint(v.y - hy), 0x7632);
    uint32_t l23 = __byte_perm(__float_as_uint(v.z - hz),
                               __float_as_uint(v.w - hw), 0x7632);
    *(uint32_t*)(sh + off)     = h01;
    *(uint32_t*)(sh + off + 2) = h23;
    *(uint32_t*)(sl + off)     = l01;
    *(uint32_t*)(sl + off + 2) = l23;
}

// ---------------------------------------------------------------------------
// 1) fused: X init (row-parallel) + degree histogram (edge-parallel)
// ---------------------------------------------------------------------------
__global__ void init_hist_kernel(const int* __restrict__ ei,
                                 int* __restrict__ degi,
                                 const float* __restrict__ movie_x,
                                 const float* __restrict__ user_emb,
                                 const float* __restrict__ movie_emb,
                                 const float* __restrict__ lin_W,
                                 const float* __restrict__ lin_b,
                                 float* __restrict__ X) {
    int gid = blockIdx.x * blockDim.x + threadIdx.x;
    if (gid < NE) atomicAdd(&degi[ei[NE + gid]], 1);

    __shared__ float sx[4][F_MOVIE];
    int lr  = threadIdx.x >> 6;
    int h   = threadIdx.x & 63;
    int row = blockIdx.x * 4 + lr;
    int mrow = row - N_USERS;
    if (row < NN && mrow >= 0 && h < F_MOVIE)
        sx[lr][h] = movie_x[mrow * F_MOVIE + h];
    __syncthreads();
    if (row >= NN) return;
    if (mrow < 0) {
        X[(size_t)row * HDIM + h] = user_emb[(size_t)row * HDIM + h];
    } else {
        float acc = lin_b[h] + movie_emb[(size_t)mrow * HDIM + h];
#pragma unroll
        for (int f = 0; f < F_MOVIE; f++)
            acc += sx[lr][f] * lin_W[h * F_MOVIE + f];
        X[(size_t)row * HDIM + h] = acc;
    }
}

// ---------------------------------------------------------------------------
// 2) parallel 3-pass exclusive scan (NO serial chain)
// ---------------------------------------------------------------------------
__global__ void scanA_kernel(const int* __restrict__ degi, int* __restrict__ bsum) {
    __shared__ int ws[8];
    int b = blockIdx.x, t = threadIdx.x;
    int i0 = b * 1024 + t * 4;
    int s = 0;
#pragma unroll
    for (int j = 0; j < 4; j++) { int i = i0 + j; s += (i < NN) ? degi[i] : 0; }
#pragma unroll
    for (int o = 16; o; o >>= 1) s += __shfl_xor_sync(0xffffffffu, s, o);
    if ((t & 31) == 0) ws[t >> 5] = s;
    __syncthreads();
    if (t == 0) {
        int tot = 0;
#pragma unroll
        for (int w = 0; w < 8; w++) tot += ws[w];
        bsum[b] = tot;
    }
}

__global__ void scanB_kernel(int* __restrict__ bsum, int* __restrict__ off) {
    __shared__ int s[512];
    int t = threadIdx.x;
    s[t] = (t < NB2) ? bsum[t] : 0;
    __syncthreads();
#pragma unroll
    for (int o = 1; o < 512; o <<= 1) {
        int x = (t >= o) ? s[t - o] : 0;
        __syncthreads();
        s[t] += x;
        __syncthreads();
    }
    int excl = (t == 0) ? 0 : s[t - 1];
    if (t < NB2) bsum[t] = excl;
    if (t == 0) off[NN] = NE;
}

__global__ void scanC_kernel(const int* __restrict__ degi,
                             const int* __restrict__ boff,
                             int* __restrict__ off, int* __restrict__ cur) {
    __shared__ int ss[256];
    int b = blockIdx.x, t = threadIdx.x;
    int i0 = b * 1024 + t * 4;
    int v[4];
    int tot = 0;
#pragma unroll
    for (int j = 0; j < 4; j++) {
        int i = i0 + j;
        v[j] = (i < NN) ? degi[i] : 0;
        tot += v[j];
    }
    ss[t] = tot;
    __syncthreads();
#pragma unroll
    for (int o = 1; o < 256; o <<= 1) {
        int x = (t >= o) ? ss[t - o] : 0;
        __syncthreads();
        ss[t] += x;
        __syncthreads();
    }
    int run = boff[b] + ((t == 0) ? 0 : ss[t - 1]);
#pragma unroll
    for (int j = 0; j < 4; j++) {
        int i = i0 + j;
        if (i < NN) { off[i] = run; cur[i] = run; }
        run += v[j];
    }
}

// ---------------------------------------------------------------------------
// 3) CSR fill — stores src*HDIM so gather needs no multiply
// ---------------------------------------------------------------------------
__global__ void fill_kernel(const int* __restrict__ ei,
                            int* __restrict__ cur, int* __restrict__ csr) {
    int e = blockIdx.x * blockDim.x + threadIdx.x;
    if (e >= NE) return;
    int src = ei[e];
    int dst = ei[NE + e];
    int p = atomicAdd(&cur[dst], 1);
    csr[p] = src * HDIM;
}

// ---------------------------------------------------------------------------
// 4) MEAN[row] = mean over neighbors — warp per row, float2 lanes, MLP=8.
//    MEAN written with streaming hint (__stcs): write-once-read-once data
//    should not evict the X/Y rows we keep re-gathering from L2.
// ---------------------------------------------------------------------------
__global__ void __launch_bounds__(256)
gather_kernel(const float* __restrict__ Xin,
              const int* __restrict__ off, const int* __restrict__ csr,
              float* __restrict__ MEAN) {
    int row  = (blockIdx.x * blockDim.x + threadIdx.x) >> 5;
    int lane = threadIdx.x & 31;
    if (row >= NN) return;
    int s0 = __ldg(&off[row]);
    int s1 = __ldg(&off[row + 1]);
    const float* Xl = Xin + lane * 2;
    float2 acc = make_float2(0.f, 0.f);
    for (int e = s0; e < s1; e += 8) {
        int idx[8];
        float2 v[8];
#pragma unroll
        for (int j = 0; j < 8; j++)
            idx[j] = (e + j < s1) ? __ldg(&csr[e + j]) : -1;
#pragma unroll
        for (int j = 0; j < 8; j++)
            v[j] = (idx[j] >= 0) ? *(const float2*)(Xl + idx[j])
                                 : make_float2(0.f, 0.f);
#pragma unroll
        for (int j = 0; j < 8; j++) { acc.x += v[j].x; acc.y += v[j].y; }
    }
    float inv = 1.f / fmaxf((float)(s1 - s0), 1.f);
    acc.x *= inv; acc.y *= inv;
    __stcs((float2*)&MEAN[(size_t)row * HDIM + lane * 2], acc);
}

// ---------------------------------------------------------------------------
// Y = act( MEAN @ Wl.T + bl + Xin @ Wr.T )  — tensor-core combine, PRELOADED.
// RPB=256, 512 threads, 180 KB smem -> 1 block/SM (16 warps, same as before)
// but HALF the blocks: halves per-layer weight reloads + block fixed costs.
// MEAN read with __ldcs (streaming).
// ---------------------------------------------------------------------------
#define RPB 256
#define CTHREADS 512
#define A_BYTES 36864      // 256 x BK x 2
#define B_BYTES 9216       // 64 x BK x 2

__device__ __forceinline__ void split_w(const float* __restrict__ W,
                                        uint16_t* sh, uint16_t* sl, int tid) {
#pragma unroll
    for (int it = 0; it < 2; it++) {
        int i = tid + it * CTHREADS;     // 64*16 = 1024
        int h = i >> 4, q = i & 15;
        float4 v = ((const float4*)W)[h * 16 + q];
        store_split(sh, sl, h * BK + q * 4, v);
    }
}

template <bool STREAM>
__device__ __forceinline__ void split_a(const float* __restrict__ SRC,
                                        int base, uint16_t* sh, uint16_t* sl,
                                        int tid) {
#pragma unroll
    for (int it = 0; it < 8; it++) {
        int i = tid + it * CTHREADS;     // 256*16 = 4096
        int r = i >> 4, q = i & 15;
        int row = base + r;
        float4 v = make_float4(0.f, 0.f, 0.f, 0.f);
        if (row < NN) {
            const float4* p = (const float4*)SRC + row * 16 + q;
            v = STREAM ? __ldcs(p) : *p;
        }
        store_split(sh, sl, r * BK + q * 4, v);
    }
}

__device__ __forceinline__ void mma_phase(uint32_t aH, uint32_t aL,
                                          uint32_t bH, uint32_t bL,
                                          float acc[8][4]) {
#pragma unroll
    for (int kc = 0; kc < 4; kc++) {
        uint32_t ah[4], al[4];
        LDSM4(ah, aH + kc * 32);
        LDSM4(al, aL + kc * 32);
#pragma unroll
        for (int p = 0; p < 4; p++) {
            uint32_t bh[4], blo[4];
            uint32_t boff = p * (16 * BK * 2) + kc * 32;
            LDSM4(bh,  bH + boff);
            LDSM4(blo, bL + boff);
            MMA16816(acc[2 * p],     ah, bh[0],  bh[1]);
            MMA16816(acc[2 * p + 1], ah, bh[2],  bh[3]);
            MMA16816(acc[2 * p],     ah, blo[0], blo[1]);
            MMA16816(acc[2 * p + 1], ah, blo[2], blo[3]);
            MMA16816(acc[2 * p],     al, bh[0],  bh[1]);
            MMA16816(acc[2 * p + 1], al, bh[2],  bh[3]);
        }
    }
}

template <bool RELU>
__global__ void __launch_bounds__(CTHREADS)
combine_kernel(const float* __restrict__ Xin, const float* __restrict__ MEAN,
               const float* __restrict__ Wl, const float* __restrict__ bl,
               const float* __restrict__ Wr, float* __restrict__ Y) {
    extern __shared__ char smem[];
    // layout: [Mh][Ml][Xh][Xl][Wlh][Wll][Wrh][Wrl]
    uint16_t* sMh  = (uint16_t*)smem;
    uint16_t* sMl  = (uint16_t*)(smem + A_BYTES);
    uint16_t* sXh  = (uint16_t*)(smem + 2 * A_BYTES);
    uint16_t* sXl  = (uint16_t*)(smem + 3 * A_BYTES);
    uint16_t* sWlh = (uint16_t*)(smem + 4 * A_BYTES);
    uint16_t* sWll = (uint16_t*)(smem + 4 * A_BYTES + B_BYTES);
    uint16_t* sWrh = (uint16_t*)(smem + 4 * A_BYTES + 2 * B_BYTES);
    uint16_t* sWrl = (uint16_t*)(smem + 4 * A_BYTES + 3 * B_BYTES);
    __shared__ float sb[64];

    int tid  = threadIdx.x;
    int lane = tid & 31;
    int w    = tid >> 5;          // 0..15, warp tile: rows [r0, r0+16)
    int base = blockIdx.x * RPB;
    int r0   = w * 16;

    if (tid < 64) sb[tid] = bl[tid];

    // preload ALL tiles, one sync
    split_w(Wl, sWlh, sWll, tid);
    split_w(Wr, sWrh, sWrl, tid);
    split_a<true >(MEAN, base, sMh, sMl, tid);
    split_a<false>(Xin,  base, sXh, sXl, tid);
    __syncthreads();

    // fragment addresses
    uint32_t aoff = (uint32_t)((r0 + (lane & 15)) * BK * 2)
                  + (uint32_t)((lane >> 4) * 16);
    uint32_t aMh = smem_u32(sMh) + aoff;
    uint32_t aMl = aMh + A_BYTES;
    uint32_t aXh = smem_u32(sXh) + aoff;
    uint32_t aXl = aXh + A_BYTES;
    int n_b = ((lane >> 4) << 3) + (lane & 7);
    int kb  = ((lane >> 3) & 1) * 16;
    uint32_t boff = (uint32_t)(n_b * BK * 2) + (uint32_t)kb;
    uint32_t aBlh = smem_u32(sWlh) + boff;
    uint32_t aBll = aBlh + B_BYTES;
    uint32_t aBrh = smem_u32(sWrh) + boff;
    uint32_t aBrl = aBrh + B_BYTES;

    // fp32 accumulators initialized with bias (d-fragment layout)
    float acc[8][4];
    int cq = (lane & 3) * 2;
#pragma unroll
    for (int nt = 0; nt < 8; nt++) {
        acc[nt][0] = sb[nt * 8 + cq];
        acc[nt][1] = sb[nt * 8 + cq + 1];
        acc[nt][2] = acc[nt][0];
        acc[nt][3] = acc[nt][1];
    }

    mma_phase(aMh, aMl, aBlh, aBll, acc);   // mean @ Wl^T
    mma_phase(aXh, aXl, aBrh, aBrl, acc);   // + x @ Wr^T

    // epilogue: d-fragment -> Y
    int rA = base + r0 + (lane >> 2);
    int rB = rA + 8;
#pragma unroll
    for (int nt = 0; nt < 8; nt++) {
        int cc = nt * 8 + cq;
        float2 vA = make_float2(acc[nt][0], acc[nt][1]);
        float2 vB = make_float2(acc[nt][2], acc[nt][3]);
        if (RELU) {
            vA.x = fmaxf(vA.x, 0.f); vA.y = fmaxf(vA.y, 0.f);
            vB.x = fmaxf(vB.x, 0.f); vB.y = fmaxf(vB.y, 0.f);
        }
        if (rA < NN) *(float2*)&Y[(size_t)rA * HDIM + cc] = vA;
        if (rB < NN) *(float2*)&Y[(size_t)rB * HDIM + cc] = vB;
    }
}

// ---------------------------------------------------------------------------
// out[e] = dot(Z[u[e]], Z[N_USERS + m[e]]) — 16 lanes per label edge, float4
// ---------------------------------------------------------------------------
__global__ void dot_kernel(const int* __restrict__ eli,
                           const float* __restrict__ Z,
                           float* __restrict__ out) {
    int gw = (blockIdx.x * blockDim.x + threadIdx.x) >> 4;
    int l  = threadIdx.x & 15;
    if (gw >= NEL) return;
    int u = __ldg(&eli[gw]);
    int m = __ldg(&eli[NEL + gw]);
    float4 a = *(const float4*)&Z[(size_t)u * HDIM + l * 4];
    float4 b = *(const float4*)&Z[(size_t)(N_USERS + m) * HDIM + l * 4];
    float s = a.x * b.x + a.y * b.y + a.z * b.z + a.w * b.w;
#pragma unroll
    for (int o = 8; o; o >>= 1) s += __shfl_xor_sync(0xffffffffu, s, o);
    if (l == 0) out[gw] = s;
}

// ---------------------------------------------------------------------------
extern "C" void kernel_launch(void* const* d_in, const int* in_sizes, int n_in,
                              void* d_out, int out_size) {
    const float* movie_x   = (const float*)d_in[0];
    const float* user_emb  = (const float*)d_in[1];
    const float* movie_emb = (const float*)d_in[2];
    const float* lin_W     = (const float*)d_in[3];
    const float* lin_b     = (const float*)d_in[4];
    const float* W1l       = (const float*)d_in[5];
    const float* b1        = (const float*)d_in[6];
    const float* W1r       = (const float*)d_in[7];
    const float* W2l       = (const float*)d_in[8];
    const float* b2        = (const float*)d_in[9];
    const float* W2r       = (const float*)d_in[10];
    const int*   ei        = (const int*)d_in[11];
    const int*   eli       = (const int*)d_in[12];
    float* out = (float*)d_out;

    float *dX, *dY, *dZ, *dM;
    int *dDEGI, *dOFF, *dCUR, *dCSR, *dBSUM;
    cudaGetSymbolAddress((void**)&dX,    g_X);
    cudaGetSymbolAddress((void**)&dY,    g_Y);
    cudaGetSymbolAddress((void**)&dZ,    g_Z);
    cudaGetSymbolAddress((void**)&dM,    g_M);
    cudaGetSymbolAddress((void**)&dDEGI, g_DEGI);
    cudaGetSymbolAddress((void**)&dOFF,  g_OFF);
    cudaGetSymbolAddress((void**)&dCUR,  g_CUR);
    cudaGetSymbolAddress((void**)&dCSR,  g_CSR);
    cudaGetSymbolAddress((void**)&dBSUM, g_BSUM);

    const size_t smemC = 4 * A_BYTES + 4 * B_BYTES;   // 184,320 B
    cudaFuncSetAttribute(combine_kernel<true>,
                         cudaFuncAttributeMaxDynamicSharedMemorySize, (int)smemC);
    cudaFuncSetAttribute(combine_kernel<false>,
                         cudaFuncAttributeMaxDynamicSharedMemorySize, (int)smemC);

    const int gridC = (NN + RPB - 1) / RPB;   // 1094
    const int gridG = (NN * 32 + 255) / 256;  // warp per row
    const int gridI = (NN + 3) / 4;           // init+hist (covers NE too)

    // ---- prologue: features + CSR ----
    cudaMemsetAsync(dDEGI, 0, NN * sizeof(int));
    init_hist_kernel<<<gridI, 256>>>(ei, dDEGI, movie_x, user_emb,
                                     movie_emb, lin_W, lin_b, dX);          // #1
    scanA_kernel<<<NB2, 256>>>(dDEGI, dBSUM);                               // #2
    scanB_kernel<<<1, 512>>>(dBSUM, dOFF);                                  // #3
    scanC_kernel<<<NB2, 256>>>(dDEGI, dBSUM, dOFF, dCUR);                   // #4
    fill_kernel<<<(NE + 255) / 256, 256>>>(ei, dCUR, dCSR);                 // #5

    // ---- layer 1 ----
    gather_kernel<<<gridG, 256>>>(dX, dOFF, dCSR, dM);                      // #6
    combine_kernel<true><<<gridC, CTHREADS, smemC>>>(dX, dM,
                                                     W1l, b1, W1r, dY);     // #7

    // ---- layer 2 ----
    gather_kernel<<<gridG, 256>>>(dY, dOFF, dCSR, dM);                      // #8
    combine_kernel<false><<<gridC, CTHREADS, smemC>>>(dY, dM,
                                                      W2l, b2, W2r, dZ);    // #9

    // ---- decode ----
    dot_kernel<<<(NEL * 16) / 256, 256>>>(eli, dZ, out);                    // #10
}

// round 15
// speedup vs baseline: 1.0105x; 1.0105x over previous
#include <cuda_runtime.h>
#include <cstddef>
#include <cstdint>

#define N_USERS 200000
#define N_MOVIES 80000
#define NN 280000
#define HDIM 64
#define F_MOVIE 20
#define NE 1250000
#define NEL 500000
#define NB2 274           // ceil(NN / 1024)
#define BK 72             // bf16 row stride (144 bytes) for MMA smem tiles

typedef unsigned long long u64;

// Scratch (static device globals: allowed; runtime allocation is not).
__device__ __align__(16) float g_X[(size_t)NN * HDIM];
__device__ __align__(16) float g_Y[(size_t)NN * HDIM];
__device__ __align__(16) float g_Z[(size_t)NN * HDIM];
__device__ __align__(16) float g_M[(size_t)NN * HDIM];
__device__ int g_DEGI[NN];
__device__ int g_OFF[NN + 1];
__device__ int g_CUR[NN];
__device__ int g_CSR[NE];      // holds src*HDIM (premultiplied)
__device__ int g_BSUM[512];

__device__ __forceinline__ uint32_t smem_u32(const void* p) {
    return (uint32_t)__cvta_generic_to_shared(p);
}

#define LDSM4(d, addr) \
    asm volatile("ldmatrix.sync.aligned.m8n8.x4.shared.b16 {%0,%1,%2,%3}, [%4];" \
                 : "=r"((d)[0]), "=r"((d)[1]), "=r"((d)[2]), "=r"((d)[3]) \
                 : "r"(addr))

#define MMA16816(acc, a, b0v, b1v) \
    asm volatile("mma.sync.aligned.m16n8k16.row.col.f32.bf16.bf16.f32 " \
                 "{%0,%1,%2,%3}, {%4,%5,%6,%7}, {%8,%9}, {%0,%1,%2,%3};" \
                 : "+f"((acc)[0]), "+f"((acc)[1]), "+f"((acc)[2]), "+f"((acc)[3]) \
                 : "r"((a)[0]), "r"((a)[1]), "r"((a)[2]), "r"((a)[3]), \
                   "r"(b0v), "r"(b1v))

// split x -> hi (truncated bf16) + lo (truncated bf16 of exact residual)
__device__ __forceinline__ void store_split(uint16_t* sh, uint16_t* sl,
                                            int off, float4 v) {
    uint32_t ux = __float_as_uint(v.x), uy = __float_as_uint(v.y);
    uint32_t uz = __float_as_uint(v.z), uw = __float_as_uint(v.w);
    float hx = __uint_as_float(ux & 0xFFFF0000u);
    float hy = __uint_as_float(uy & 0xFFFF0000u);
    float hz = __uint_as_float(uz & 0xFFFF0000u);
    float hw = __uint_as_float(uw & 0xFFFF0000u);
    uint32_t h01 = __byte_perm(ux, uy, 0x7632);
    uint32_t h23 = __byte_perm(uz, uw, 0x7632);
    uint32_t l01 = __byte_perm(__float_as_uint(v.x - hx),
                               __float_as_uint(v.y - hy), 0x7632);
    uint32_t l23 = __byte_perm(__float_as_uint(v.z - hz),
                               __float_as_uint(v.w - hw), 0x7632);
    *(uint32_t*)(sh + off)     = h01;
    *(uint32_t*)(sh + off + 2) = h23;
    *(uint32_t*)(sl + off)     = l01;
    *(uint32_t*)(sl + off + 2) = l23;
}

// ---------------------------------------------------------------------------
// 1) fused: X init (row-parallel) + degree histogram (edge-parallel)
// ---------------------------------------------------------------------------
__global__ void init_hist_kernel(const int* __restrict__ ei,
                                 int* __restrict__ degi,
                                 const float* __restrict__ movie_x,
                                 const float* __restrict__ user_emb,
                                 const float* __restrict__ movie_emb,
                                 const float* __restrict__ lin_W,
                                 const float* __restrict__ lin_b,
                                 float* __restrict__ X) {
    int gid = blockIdx.x * blockDim.x + threadIdx.x;
    if (gid < NE) atomicAdd(&degi[ei[NE + gid]], 1);

    __shared__ float sx[4][F_MOVIE];
    int lr  = threadIdx.x >> 6;
    int h   = threadIdx.x & 63;
    int row = blockIdx.x * 4 + lr;
    int mrow = row - N_USERS;
    if (row < NN && mrow >= 0 && h < F_MOVIE)
        sx[lr][h] = movie_x[mrow * F_MOVIE + h];
    __syncthreads();
    if (row >= NN) return;
    if (mrow < 0) {
        X[(size_t)row * HDIM + h] = user_emb[(size_t)row * HDIM + h];
    } else {
        float acc = lin_b[h] + movie_emb[(size_t)mrow * HDIM + h];
#pragma unroll
        for (int f = 0; f < F_MOVIE; f++)
            acc += sx[lr][f] * lin_W[h * F_MOVIE + f];
        X[(size_t)row * HDIM + h] = acc;
    }
}

// ---------------------------------------------------------------------------
// 2) parallel 3-pass exclusive scan (NO serial chain)
// ---------------------------------------------------------------------------
__global__ void scanA_kernel(const int* __restrict__ degi, int* __restrict__ bsum) {
    __shared__ int ws[8];
    int b = blockIdx.x, t = threadIdx.x;
    int i0 = b * 1024 + t * 4;
    int s = 0;
#pragma unroll
    for (int j = 0; j < 4; j++) { int i = i0 + j; s += (i < NN) ? degi[i] : 0; }
#pragma unroll
    for (int o = 16; o; o >>= 1) s += __shfl_xor_sync(0xffffffffu, s, o);
    if ((t & 31) == 0) ws[t >> 5] = s;
    __syncthreads();
    if (t == 0) {
        int tot = 0;
#pragma unroll
        for (int w = 0; w < 8; w++) tot += ws[w];
        bsum[b] = tot;
    }
}

__global__ void scanB_kernel(int* __restrict__ bsum, int* __restrict__ off) {
    __shared__ int s[512];
    int t = threadIdx.x;
    s[t] = (t < NB2) ? bsum[t] : 0;
    __syncthreads();
#pragma unroll
    for (int o = 1; o < 512; o <<= 1) {
        int x = (t >= o) ? s[t - o] : 0;
        __syncthreads();
        s[t] += x;
        __syncthreads();
    }
    int excl = (t == 0) ? 0 : s[t - 1];
    if (t < NB2) bsum[t] = excl;
    if (t == 0) off[NN] = NE;
}

__global__ void scanC_kernel(const int* __restrict__ degi,
                             const int* __restrict__ boff,
                             int* __restrict__ off, int* __restrict__ cur) {
    __shared__ int ss[256];
    int b = blockIdx.x, t = threadIdx.x;
    int i0 = b * 1024 + t * 4;
    int v[4];
    int tot = 0;
#pragma unroll
    for (int j = 0; j < 4; j++) {
        int i = i0 + j;
        v[j] = (i < NN) ? degi[i] : 0;
        tot += v[j];
    }
    ss[t] = tot;
    __syncthreads();
#pragma unroll
    for (int o = 1; o < 256; o <<= 1) {
        int x = (t >= o) ? ss[t - o] : 0;
        __syncthreads();
        ss[t] += x;
        __syncthreads();
    }
    int run = boff[b] + ((t == 0) ? 0 : ss[t - 1]);
#pragma unroll
    for (int j = 0; j < 4; j++) {
        int i = i0 + j;
        if (i < NN) { off[i] = run; cur[i] = run; }
        run += v[j];
    }
}

// ---------------------------------------------------------------------------
// 3) CSR fill — stores src*HDIM so gather needs no multiply
// ---------------------------------------------------------------------------
__global__ void fill_kernel(const int* __restrict__ ei,
                            int* __restrict__ cur, int* __restrict__ csr) {
    int e = blockIdx.x * blockDim.x + threadIdx.x;
    if (e >= NE) return;
    int src = ei[e];
    int dst = ei[NE + e];
    int p = atomicAdd(&cur[dst], 1);
    csr[p] = src * HDIM;
}

// ---------------------------------------------------------------------------
// 4) MEAN[row] = mean over neighbors — warp per row, float2 lanes, MLP=8.
//    MEAN stored with streaming hint: write-once-read-once data must not
//    evict the X/Y rows we keep re-gathering from L2.
// ---------------------------------------------------------------------------
__global__ void __launch_bounds__(256)
gather_kernel(const float* __restrict__ Xin,
              const int* __restrict__ off, const int* __restrict__ csr,
              float* __restrict__ MEAN) {
    int row  = (blockIdx.x * blockDim.x + threadIdx.x) >> 5;
    int lane = threadIdx.x & 31;
    if (row >= NN) return;
    int s0 = __ldg(&off[row]);
    int s1 = __ldg(&off[row + 1]);
    const float* Xl = Xin + lane * 2;
    float2 acc = make_float2(0.f, 0.f);
    for (int e = s0; e < s1; e += 8) {
        int idx[8];
        float2 v[8];
#pragma unroll
        for (int j = 0; j < 8; j++)
            idx[j] = (e + j < s1) ? __ldg(&csr[e + j]) : -1;
#pragma unroll
        for (int j = 0; j < 8; j++)
            v[j] = (idx[j] >= 0) ? *(const float2*)(Xl + idx[j])
                                 : make_float2(0.f, 0.f);
#pragma unroll
        for (int j = 0; j < 8; j++) { acc.x += v[j].x; acc.y += v[j].y; }
    }
    float inv = 1.f / fmaxf((float)(s1 - s0), 1.f);
    acc.x *= inv; acc.y *= inv;
    __stcs((float2*)&MEAN[(size_t)row * HDIM + lane * 2], acc);
}

// ---------------------------------------------------------------------------
// Y = act( MEAN @ Wl.T + bl + Xin @ Wr.T )  — tensor-core combine, PRELOADED,
// R13 shape: RPB=128, 256 threads, 110.6 KB smem -> 2 blocks/SM (overlap of
// one block's load/split phase with the other's MMA stream is load-bearing).
// MEAN read with __ldcs (streaming, read-once).
// ---------------------------------------------------------------------------
#define RPB 128
#define A_BYTES 18432      // 128 x BK x 2
#define B_BYTES 9216       // 64 x BK x 2

__device__ __forceinline__ void split_w(const float* __restrict__ W,
                                        uint16_t* sh, uint16_t* sl, int tid) {
#pragma unroll
    for (int it = 0; it < 4; it++) {
        int i = tid + it * 256;          // 64*16 = 1024
        int h = i >> 4, q = i & 15;
        float4 v = ((const float4*)W)[h * 16 + q];
        store_split(sh, sl, h * BK + q * 4, v);
    }
}

template <bool STREAM>
__device__ __forceinline__ void split_a(const float* __restrict__ SRC,
                                        int base, uint16_t* sh, uint16_t* sl,
                                        int tid) {
#pragma unroll
    for (int it = 0; it < 8; it++) {
        int i = tid + it * 256;          // 128*16 = 2048
        int r = i >> 4, q = i & 15;
        int row = base + r;
        float4 v = make_float4(0.f, 0.f, 0.f, 0.f);
        if (row < NN) {
            const float4* p = (const float4*)SRC + row * 16 + q;
            v = STREAM ? __ldcs(p) : *p;
        }
        store_split(sh, sl, r * BK + q * 4, v);
    }
}

__device__ __forceinline__ void mma_phase(uint32_t aH, uint32_t aL,
                                          uint32_t bH, uint32_t bL,
                                          float acc[8][4]) {
#pragma unroll
    for (int kc = 0; kc < 4; kc++) {
        uint32_t ah[4], al[4];
        LDSM4(ah, aH + kc * 32);
        LDSM4(al, aL + kc * 32);
#pragma unroll
        for (int p = 0; p < 4; p++) {
            uint32_t bh[4], blo[4];
            uint32_t boff = p * (16 * BK * 2) + kc * 32;
            LDSM4(bh,  bH + boff);
            LDSM4(blo, bL + boff);
            MMA16816(acc[2 * p],     ah, bh[0],  bh[1]);
            MMA16816(acc[2 * p + 1], ah, bh[2],  bh[3]);
            MMA16816(acc[2 * p],     ah, blo[0], blo[1]);
            MMA16816(acc[2 * p + 1], ah, blo[2], blo[3]);
            MMA16816(acc[2 * p],     al, bh[0],  bh[1]);
            MMA16816(acc[2 * p + 1], al, bh[2],  bh[3]);
        }
    }
}

template <bool RELU>
__global__ void __launch_bounds__(256)
combine_kernel(const float* __restrict__ Xin, const float* __restrict__ MEAN,
               const float* __restrict__ Wl, const float* __restrict__ bl,
               const float* __restrict__ Wr, float* __restrict__ Y) {
    extern __shared__ char smem[];
    // layout: [Mh][Ml][Xh][Xl][Wlh][Wll][Wrh][Wrl]
    uint16_t* sMh  = (uint16_t*)smem;
    uint16_t* sMl  = (uint16_t*)(smem + A_BYTES);
    uint16_t* sXh  = (uint16_t*)(smem + 2 * A_BYTES);
    uint16_t* sXl  = (uint16_t*)(smem + 3 * A_BYTES);
    uint16_t* sWlh = (uint16_t*)(smem + 4 * A_BYTES);
    uint16_t* sWll = (uint16_t*)(smem + 4 * A_BYTES + B_BYTES);
    uint16_t* sWrh = (uint16_t*)(smem + 4 * A_BYTES + 2 * B_BYTES);
    uint16_t* sWrl = (uint16_t*)(smem + 4 * A_BYTES + 3 * B_BYTES);
    __shared__ float sb[64];

    int tid  = threadIdx.x;
    int lane = tid & 31;
    int w    = tid >> 5;          // 0..7, warp tile: rows [r0, r0+16)
    int base = blockIdx.x * RPB;
    int r0   = w * 16;

    if (tid < 64) sb[tid] = bl[tid];

    // preload ALL tiles, one sync
    split_w(Wl, sWlh, sWll, tid);
    split_w(Wr, sWrh, sWrl, tid);
    split_a<true >(MEAN, base, sMh, sMl, tid);
    split_a<false>(Xin,  base, sXh, sXl, tid);
    __syncthreads();

    // fragment addresses
    uint32_t aoff = (uint32_t)((r0 + (lane & 15)) * BK * 2)
                  + (uint32_t)((lane >> 4) * 16);
    uint32_t aMh = smem_u32(sMh) + aoff;
    uint32_t aMl = aMh + A_BYTES;
    uint32_t aXh = smem_u32(sXh) + aoff;
    uint32_t aXl = aXh + A_BYTES;
    int n_b = ((lane >> 4) << 3) + (lane & 7);
    int kb  = ((lane >> 3) & 1) * 16;
    uint32_t boff = (uint32_t)(n_b * BK * 2) + (uint32_t)kb;
    uint32_t aBlh = smem_u32(sWlh) + boff;
    uint32_t aBll = aBlh + B_BYTES;
    uint32_t aBrh = smem_u32(sWrh) + boff;
    uint32_t aBrl = aBrh + B_BYTES;

    // fp32 accumulators initialized with bias (d-fragment layout)
    float acc[8][4];
    int cq = (lane & 3) * 2;
#pragma unroll
    for (int nt = 0; nt < 8; nt++) {
        acc[nt][0] = sb[nt * 8 + cq];
        acc[nt][1] = sb[nt * 8 + cq + 1];
        acc[nt][2] = acc[nt][0];
        acc[nt][3] = acc[nt][1];
    }

    mma_phase(aMh, aMl, aBlh, aBll, acc);   // mean @ Wl^T
    mma_phase(aXh, aXl, aBrh, aBrl, acc);   // + x @ Wr^T

    // epilogue: d-fragment -> Y
    int rA = base + r0 + (lane >> 2);
    int rB = rA + 8;
#pragma unroll
    for (int nt = 0; nt < 8; nt++) {
        int cc = nt * 8 + cq;
        float2 vA = make_float2(acc[nt][0], acc[nt][1]);
        float2 vB = make_float2(acc[nt][2], acc[nt][3]);
        if (RELU) {
            vA.x = fmaxf(vA.x, 0.f); vA.y = fmaxf(vA.y, 0.f);
            vB.x = fmaxf(vB.x, 0.f); vB.y = fmaxf(vB.y, 0.f);
        }
        if (rA < NN) *(float2*)&Y[(size_t)rA * HDIM + cc] = vA;
        if (rB < NN) *(float2*)&Y[(size_t)rB * HDIM + cc] = vB;
    }
}

// ---------------------------------------------------------------------------
// out[e] = dot(Z[u[e]], Z[N_USERS + m[e]]) — 16 lanes per label edge, float4
// ---------------------------------------------------------------------------
__global__ void dot_kernel(const int* __restrict__ eli,
                           const float* __restrict__ Z,
                           float* __restrict__ out) {
    int gw = (blockIdx.x * blockDim.x + threadIdx.x) >> 4;
    int l  = threadIdx.x & 15;
    if (gw >= NEL) return;
    int u = __ldg(&eli[gw]);
    int m = __ldg(&eli[NEL + gw]);
    float4 a = *(const float4*)&Z[(size_t)u * HDIM + l * 4];
    float4 b = *(const float4*)&Z[(size_t)(N_USERS + m) * HDIM + l * 4];
    float s = a.x * b.x + a.y * b.y + a.z * b.z + a.w * b.w;
#pragma unroll
    for (int o = 8; o; o >>= 1) s += __shfl_xor_sync(0xffffffffu, s, o);
    if (l == 0) out[gw] = s;
}

// ---------------------------------------------------------------------------
extern "C" void kernel_launch(void* const* d_in, const int* in_sizes, int n_in,
                              void* d_out, int out_size) {
    const float* movie_x   = (const float*)d_in[0];
    const float* user_emb  = (const float*)d_in[1];
    const float* movie_emb = (const float*)d_in[2];
    const float* lin_W     = (const float*)d_in[3];
    const float* lin_b     = (const float*)d_in[4];
    const float* W1l       = (const float*)d_in[5];
    const float* b1        = (const float*)d_in[6];
    const float* W1r       = (const float*)d_in[7];
    const float* W2l       = (const float*)d_in[8];
    const float* b2        = (const float*)d_in[9];
    const float* W2r       = (const float*)d_in[10];
    const int*   ei        = (const int*)d_in[11];
    const int*   eli       = (const int*)d_in[12];
    float* out = (float*)d_out;

    float *dX, *dY, *dZ, *dM;
    int *dDEGI, *dOFF, *dCUR, *dCSR, *dBSUM;
    cudaGetSymbolAddress((void**)&dX,    g_X);
    cudaGetSymbolAddress((void**)&dY,    g_Y);
    cudaGetSymbolAddress((void**)&dZ,    g_Z);
    cudaGetSymbolAddress((void**)&dM,    g_M);
    cudaGetSymbolAddress((void**)&dDEGI, g_DEGI);
    cudaGetSymbolAddress((void**)&dOFF,  g_OFF);
    cudaGetSymbolAddress((void**)&dCUR,  g_CUR);
    cudaGetSymbolAddress((void**)&dCSR,  g_CSR);
    cudaGetSymbolAddress((void**)&dBSUM, g_BSUM);

    const size_t smemC = 4 * A_BYTES + 4 * B_BYTES;   // 110,592 B
    cudaFuncSetAttribute(combine_kernel<true>,
                         cudaFuncAttributeMaxDynamicSharedMemorySize, (int)smemC);
    cudaFuncSetAttribute(combine_kernel<false>,
                         cudaFuncAttributeMaxDynamicSharedMemorySize, (int)smemC);

    const int gridC = (NN + RPB - 1) / RPB;   // 2188
    const int gridG = (NN * 32 + 255) / 256;  // warp per row
    const int gridI = (NN + 3) / 4;           // init+hist (covers NE too)

    // ---- prologue: features + CSR ----
    cudaMemsetAsync(dDEGI, 0, NN * sizeof(int));
    init_hist_kernel<<<gridI, 256>>>(ei, dDEGI, movie_x, user_emb,
                                     movie_emb, lin_W, lin_b, dX);          // #1
    scanA_kernel<<<NB2, 256>>>(dDEGI, dBSUM);                               // #2
    scanB_kernel<<<1, 512>>>(dBSUM, dOFF);                                  // #3
    scanC_kernel<<<NB2, 256>>>(dDEGI, dBSUM, dOFF, dCUR);                   // #4
    fill_kernel<<<(NE + 255) / 256, 256>>>(ei, dCUR, dCSR);                 // #5

    // ---- layer 1 ----
    gather_kernel<<<gridG, 256>>>(dX, dOFF, dCSR, dM);                      // #6
    combine_kernel<true><<<gridC, 256, smemC>>>(dX, dM, W1l, b1, W1r, dY);  // #7

    // ---- layer 2 ----
    gather_kernel<<<gridG, 256>>>(dY, dOFF, dCSR, dM);                      // #8
    combine_kernel<false><<<gridC, 256, smemC>>>(dY, dM, W2l, b2, W2r, dZ); // #9

    // ---- decode ----
    dot_kernel<<<(NEL * 16) / 256, 256>>>(eli, dZ, out);                    // #10
}

// round 16
// speedup vs baseline: 1.0917x; 1.0804x over previous
#include <cuda_runtime.h>
#include <cstddef>
#include <cstdint>

#define N_USERS 200000
#define N_MOVIES 80000
#define NN 280000
#define HDIM 64
#define F_MOVIE 20
#define NE 1250000
#define NEL 500000
#define NB2 274           // ceil(NN / 1024)
#define BK 72             // bf16 row stride (144 bytes) for MMA smem tiles

typedef unsigned long long u64;

// Scratch (static device globals: allowed; runtime allocation is not).
__device__ __align__(16) float g_X[(size_t)NN * HDIM];
__device__ __align__(16) float g_Y[(size_t)NN * HDIM];
__device__ __align__(16) float g_Z[(size_t)NN * HDIM];
__device__ __align__(16) float g_M[(size_t)NN * HDIM];
__device__ int g_DEGI[NN];
__device__ int g_OFF[NN + 1];
__device__ int g_CUR[NN];
__device__ int g_CSR[NE];      // holds src*HDIM (premultiplied)
__device__ int g_BSUM[512];

__device__ __forceinline__ uint32_t smem_u32(const void* p) {
    return (uint32_t)__cvta_generic_to_shared(p);
}

#define LDSM4(d, addr) \
    asm volatile("ldmatrix.sync.aligned.m8n8.x4.shared.b16 {%0,%1,%2,%3}, [%4];" \
                 : "=r"((d)[0]), "=r"((d)[1]), "=r"((d)[2]), "=r"((d)[3]) \
                 : "r"(addr))

#define MMA16816(acc, a, b0v, b1v) \
    asm volatile("mma.sync.aligned.m16n8k16.row.col.f32.bf16.bf16.f32 " \
                 "{%0,%1,%2,%3}, {%4,%5,%6,%7}, {%8,%9}, {%0,%1,%2,%3};" \
                 : "+f"((acc)[0]), "+f"((acc)[1]), "+f"((acc)[2]), "+f"((acc)[3]) \
                 : "r"((a)[0]), "r"((a)[1]), "r"((a)[2]), "r"((a)[3]), \
                   "r"(b0v), "r"(b1v))

// split x -> hi (truncated bf16) + lo (truncated bf16 of exact residual)
__device__ __forceinline__ void store_split(uint16_t* sh, uint16_t* sl,
                                            int off, float4 v) {
    uint32_t ux = __float_as_uint(v.x), uy = __float_as_uint(v.y);
    uint32_t uz = __float_as_uint(v.z), uw = __float_as_uint(v.w);
    float hx = __uint_as_float(ux & 0xFFFF0000u);
    float hy = __uint_as_float(uy & 0xFFFF0000u);
    float hz = __uint_as_float(uz & 0xFFFF0000u);
    float hw = __uint_as_float(uw & 0xFFFF0000u);
    uint32_t h01 = __byte_perm(ux, uy, 0x7632);
    uint32_t h23 = __byte_perm(uz, uw, 0x7632);
    uint32_t l01 = __byte_perm(__float_as_uint(v.x - hx),
                               __float_as_uint(v.y - hy), 0x7632);
    uint32_t l23 = __byte_perm(__float_as_uint(v.z - hz),
                               __float_as_uint(v.w - hw), 0x7632);
    *(uint32_t*)(sh + off)     = h01;
    *(uint32_t*)(sh + off + 2) = h23;
    *(uint32_t*)(sl + off)     = l01;
    *(uint32_t*)(sl + off + 2) = l23;
}

// ---------------------------------------------------------------------------
// 1) fused: X init (row-parallel) + degree histogram (edge-parallel)
// ---------------------------------------------------------------------------
__global__ void init_hist_kernel(const int* __restrict__ ei,
                                 int* __restrict__ degi,
                                 const float* __restrict__ movie_x,
                                 const float* __restrict__ user_emb,
                                 const float* __restrict__ movie_emb,
                                 const float* __restrict__ lin_W,
                                 const float* __restrict__ lin_b,
                                 float* __restrict__ X) {
    int gid = blockIdx.x * blockDim.x + threadIdx.x;
    if (gid < NE) atomicAdd(&degi[ei[NE + gid]], 1);

    __shared__ float sx[4][F_MOVIE];
    int lr  = threadIdx.x >> 6;
    int h   = threadIdx.x & 63;
    int row = blockIdx.x * 4 + lr;
    int mrow = row - N_USERS;
    if (row < NN && mrow >= 0 && h < F_MOVIE)
        sx[lr][h] = movie_x[mrow * F_MOVIE + h];
    __syncthreads();
    if (row >= NN) return;
    if (mrow < 0) {
        X[(size_t)row * HDIM + h] = user_emb[(size_t)row * HDIM + h];
    } else {
        float acc = lin_b[h] + movie_emb[(size_t)mrow * HDIM + h];
#pragma unroll
        for (int f = 0; f < F_MOVIE; f++)
            acc += sx[lr][f] * lin_W[h * F_MOVIE + f];
        X[(size_t)row * HDIM + h] = acc;
    }
}

// ---------------------------------------------------------------------------
// 2) parallel 3-pass exclusive scan (NO serial chain)
// ---------------------------------------------------------------------------
__global__ void scanA_kernel(const int* __restrict__ degi, int* __restrict__ bsum) {
    __shared__ int ws[8];
    int b = blockIdx.x, t = threadIdx.x;
    int i0 = b * 1024 + t * 4;
    int s = 0;
#pragma unroll
    for (int j = 0; j < 4; j++) { int i = i0 + j; s += (i < NN) ? degi[i] : 0; }
#pragma unroll
    for (int o = 16; o; o >>= 1) s += __shfl_xor_sync(0xffffffffu, s, o);
    if ((t & 31) == 0) ws[t >> 5] = s;
    __syncthreads();
    if (t == 0) {
        int tot = 0;
#pragma unroll
        for (int w = 0; w < 8; w++) tot += ws[w];
        bsum[b] = tot;
    }
}

__global__ void scanB_kernel(int* __restrict__ bsum, int* __restrict__ off) {
    __shared__ int s[512];
    int t = threadIdx.x;
    s[t] = (t < NB2) ? bsum[t] : 0;
    __syncthreads();
#pragma unroll
    for (int o = 1; o < 512; o <<= 1) {
        int x = (t >= o) ? s[t - o] : 0;
        __syncthreads();
        s[t] += x;
        __syncthreads();
    }
    int excl = (t == 0) ? 0 : s[t - 1];
    if (t < NB2) bsum[t] = excl;
    if (t == 0) off[NN] = NE;
}

__global__ void scanC_kernel(const int* __restrict__ degi,
                             const int* __restrict__ boff,
                             int* __restrict__ off, int* __restrict__ cur) {
    __shared__ int ss[256];
    int b = blockIdx.x, t = threadIdx.x;
    int i0 = b * 1024 + t * 4;
    int v[4];
    int tot = 0;
#pragma unroll
    for (int j = 0; j < 4; j++) {
        int i = i0 + j;
        v[j] = (i < NN) ? degi[i] : 0;
        tot += v[j];
    }
    ss[t] = tot;
    __syncthreads();
#pragma unroll
    for (int o = 1; o < 256; o <<= 1) {
        int x = (t >= o) ? ss[t - o] : 0;
        __syncthreads();
        ss[t] += x;
        __syncthreads();
    }
    int run = boff[b] + ((t == 0) ? 0 : ss[t - 1]);
#pragma unroll
    for (int j = 0; j < 4; j++) {
        int i = i0 + j;
        if (i < NN) { off[i] = run; cur[i] = run; }
        run += v[j];
    }
}

// ---------------------------------------------------------------------------
// 3) CSR fill — stores src*HDIM so gather needs no multiply
// ---------------------------------------------------------------------------
__global__ void fill_kernel(const int* __restrict__ ei,
                            int* __restrict__ cur, int* __restrict__ csr) {
    int e = blockIdx.x * blockDim.x + threadIdx.x;
    if (e >= NE) return;
    int src = ei[e];
    int dst = ei[NE + e];
    int p = atomicAdd(&cur[dst], 1);
    csr[p] = src * HDIM;
}

// ---------------------------------------------------------------------------
// 4) MEAN[row] = mean over neighbors — warp per row, float2 lanes, MLP=8.
//    Default caching (streaming hints measured -32 us: MEAN must stay in L2
//    for the immediately-following combine reads).
// ---------------------------------------------------------------------------
__global__ void __launch_bounds__(256)
gather_kernel(const float* __restrict__ Xin,
              const int* __restrict__ off, const int* __restrict__ csr,
              float* __restrict__ MEAN) {
    int row  = (blockIdx.x * blockDim.x + threadIdx.x) >> 5;
    int lane = threadIdx.x & 31;
    if (row >= NN) return;
    int s0 = __ldg(&off[row]);
    int s1 = __ldg(&off[row + 1]);
    const float* Xl = Xin + lane * 2;
    float2 acc = make_float2(0.f, 0.f);
    for (int e = s0; e < s1; e += 8) {
        int idx[8];
        float2 v[8];
#pragma unroll
        for (int j = 0; j < 8; j++)
            idx[j] = (e + j < s1) ? __ldg(&csr[e + j]) : -1;
#pragma unroll
        for (int j = 0; j < 8; j++)
            v[j] = (idx[j] >= 0) ? *(const float2*)(Xl + idx[j])
                                 : make_float2(0.f, 0.f);
#pragma unroll
        for (int j = 0; j < 8; j++) { acc.x += v[j].x; acc.y += v[j].y; }
    }
    float inv = 1.f / fmaxf((float)(s1 - s0), 1.f);
    acc.x *= inv; acc.y *= inv;
    *(float2*)&MEAN[(size_t)row * HDIM + lane * 2] = acc;
}

// ---------------------------------------------------------------------------
// Y = act( MEAN @ Wl.T + bl + Xin @ Wr.T )  — tensor-core combine, PRELOADED.
// R13 measured optimum: RPB=128, 256 threads, 110.6 KB smem -> 2 blocks/SM
// (co-residency overlaps one block's load/split phase with the other's MMA
// stream — load-bearing; RPB=256/1-block measured +35 us).
// ---------------------------------------------------------------------------
#define RPB 128
#define A_BYTES 18432      // 128 x BK x 2
#define B_BYTES 9216       // 64 x BK x 2

__device__ __forceinline__ void split_w(const float* __restrict__ W,
                                        uint16_t* sh, uint16_t* sl, int tid) {
#pragma unroll
    for (int it = 0; it < 4; it++) {
        int i = tid + it * 256;          // 64*16 = 1024
        int h = i >> 4, q = i & 15;
        float4 v = ((const float4*)W)[h * 16 + q];
        store_split(sh, sl, h * BK + q * 4, v);
    }
}

__device__ __forceinline__ void split_a(const float* __restrict__ SRC,
                                        int base, uint16_t* sh, uint16_t* sl,
                                        int tid) {
#pragma unroll
    for (int it = 0; it < 8; it++) {
        int i = tid + it * 256;          // 128*16 = 2048
        int r = i >> 4, q = i & 15;
        int row = base + r;
        float4 v = make_float4(0.f, 0.f, 0.f, 0.f);
        if (row < NN) v = ((const float4*)SRC)[row * 16 + q];
        store_split(sh, sl, r * BK + q * 4, v);
    }
}

__device__ __forceinline__ void mma_phase(uint32_t aH, uint32_t aL,
                                          uint32_t bH, uint32_t bL,
                                          float acc[8][4]) {
#pragma unroll
    for (int kc = 0; kc < 4; kc++) {
        uint32_t ah[4], al[4];
        LDSM4(ah, aH + kc * 32);
        LDSM4(al, aL + kc * 32);
#pragma unroll
        for (int p = 0; p < 4; p++) {
            uint32_t bh[4], blo[4];
            uint32_t boff = p * (16 * BK * 2) + kc * 32;
            LDSM4(bh,  bH + boff);
            LDSM4(blo, bL + boff);
            MMA16816(acc[2 * p],     ah, bh[0],  bh[1]);
            MMA16816(acc[2 * p + 1], ah, bh[2],  bh[3]);
            MMA16816(acc[2 * p],     ah, blo[0], blo[1]);
            MMA16816(acc[2 * p + 1], ah, blo[2], blo[3]);
            MMA16816(acc[2 * p],     al, bh[0],  bh[1]);
            MMA16816(acc[2 * p + 1], al, bh[2],  bh[3]);
        }
    }
}

template <bool RELU>
__global__ void __launch_bounds__(256)
combine_kernel(const float* __restrict__ Xin, const float* __restrict__ MEAN,
               const float* __restrict__ Wl, const float* __restrict__ bl,
               const float* __restrict__ Wr, float* __restrict__ Y) {
    extern __shared__ char smem[];
    // layout: [Mh][Ml][Xh][Xl][Wlh][Wll][Wrh][Wrl]
    uint16_t* sMh  = (uint16_t*)smem;
    uint16_t* sMl  = (uint16_t*)(smem + A_BYTES);
    uint16_t* sXh  = (uint16_t*)(smem + 2 * A_BYTES);
    uint16_t* sXl  = (uint16_t*)(smem + 3 * A_BYTES);
    uint16_t* sWlh = (uint16_t*)(smem + 4 * A_BYTES);
    uint16_t* sWll = (uint16_t*)(smem + 4 * A_BYTES + B_BYTES);
    uint16_t* sWrh = (uint16_t*)(smem + 4 * A_BYTES + 2 * B_BYTES);
    uint16_t* sWrl = (uint16_t*)(smem + 4 * A_BYTES + 3 * B_BYTES);
    __shared__ float sb[64];

    int tid  = threadIdx.x;
    int lane = tid & 31;
    int w    = tid >> 5;          // 0..7, warp tile: rows [r0, r0+16)
    int base = blockIdx.x * RPB;
    int r0   = w * 16;

    if (tid < 64) sb[tid] = bl[tid];

    // preload ALL tiles, one sync
    split_w(Wl, sWlh, sWll, tid);
    split_w(Wr, sWrh, sWrl, tid);
    split_a(MEAN, base, sMh, sMl, tid);
    split_a(Xin,  base, sXh, sXl, tid);
    __syncthreads();

    // fragment addresses
    uint32_t aoff = (uint32_t)((r0 + (lane & 15)) * BK * 2)
                  + (uint32_t)((lane >> 4) * 16);
    uint32_t aMh = smem_u32(sMh) + aoff;
    uint32_t aMl = aMh + A_BYTES;
    uint32_t aXh = smem_u32(sXh) + aoff;
    uint32_t aXl = aXh + A_BYTES;
    int n_b = ((lane >> 4) << 3) + (lane & 7);
    int kb  = ((lane >> 3) & 1) * 16;
    uint32_t boff = (uint32_t)(n_b * BK * 2) + (uint32_t)kb;
    uint32_t aBlh = smem_u32(sWlh) + boff;
    uint32_t aBll = aBlh + B_BYTES;
    uint32_t aBrh = smem_u32(sWrh) + boff;
    uint32_t aBrl = aBrh + B_BYTES;

    // fp32 accumulators initialized with bias (d-fragment layout)
    float acc[8][4];
    int cq = (lane & 3) * 2;
#pragma unroll
    for (int nt = 0; nt < 8; nt++) {
        acc[nt][0] = sb[nt * 8 + cq];
        acc[nt][1] = sb[nt * 8 + cq + 1];
        acc[nt][2] = acc[nt][0];
        acc[nt][3] = acc[nt][1];
    }

    mma_phase(aMh, aMl, aBlh, aBll, acc);   // mean @ Wl^T
    mma_phase(aXh, aXl, aBrh, aBrl, acc);   // + x @ Wr^T

    // epilogue: d-fragment -> Y
    int rA = base + r0 + (lane >> 2);
    int rB = rA + 8;
#pragma unroll
    for (int nt = 0; nt < 8; nt++) {
        int cc = nt * 8 + cq;
        float2 vA = make_float2(acc[nt][0], acc[nt][1]);
        float2 vB = make_float2(acc[nt][2], acc[nt][3]);
        if (RELU) {
            vA.x = fmaxf(vA.x, 0.f); vA.y = fmaxf(vA.y, 0.f);
            vB.x = fmaxf(vB.x, 0.f); vB.y = fmaxf(vB.y, 0.f);
        }
        if (rA < NN) *(float2*)&Y[(size_t)rA * HDIM + cc] = vA;
        if (rB < NN) *(float2*)&Y[(size_t)rB * HDIM + cc] = vB;
    }
}

// ---------------------------------------------------------------------------
// out[e] = dot(Z[u[e]], Z[N_USERS + m[e]]) — 16 lanes per label edge, float4
// ---------------------------------------------------------------------------
__global__ void dot_kernel(const int* __restrict__ eli,
                           const float* __restrict__ Z,
                           float* __restrict__ out) {
    int gw = (blockIdx.x * blockDim.x + threadIdx.x) >> 4;
    int l  = threadIdx.x & 15;
    if (gw >= NEL) return;
    int u = __ldg(&eli[gw]);
    int m = __ldg(&eli[NEL + gw]);
    float4 a = *(const float4*)&Z[(size_t)u * HDIM + l * 4];
    float4 b = *(const float4*)&Z[(size_t)(N_USERS + m) * HDIM + l * 4];
    float s = a.x * b.x + a.y * b.y + a.z * b.z + a.w * b.w;
#pragma unroll
    for (int o = 8; o; o >>= 1) s += __shfl_xor_sync(0xffffffffu, s, o);
    if (l == 0) out[gw] = s;
}

// ---------------------------------------------------------------------------
extern "C" void kernel_launch(void* const* d_in, const int* in_sizes, int n_in,
                              void* d_out, int out_size) {
    const float* movie_x   = (const float*)d_in[0];
    const float* user_emb  = (const float*)d_in[1];
    const float* movie_emb = (const float*)d_in[2];
    const float* lin_W     = (const float*)d_in[3];
    const float* lin_b     = (const float*)d_in[4];
    const float* W1l       = (const float*)d_in[5];
    const float* b1        = (const float*)d_in[6];
    const float* W1r       = (const float*)d_in[7];
    const float* W2l       = (const float*)d_in[8];
    const float* b2        = (const float*)d_in[9];
    const float* W2r       = (const float*)d_in[10];
    const int*   ei        = (const int*)d_in[11];
    const int*   eli       = (const int*)d_in[12];
    float* out = (float*)d_out;

    float *dX, *dY, *dZ, *dM;
    int *dDEGI, *dOFF, *dCUR, *dCSR, *dBSUM;
    cudaGetSymbolAddress((void**)&dX,    g_X);
    cudaGetSymbolAddress((void**)&dY,    g_Y);
    cudaGetSymbolAddress((void**)&dZ,    g_Z);
    cudaGetSymbolAddress((void**)&dM,    g_M);
    cudaGetSymbolAddress((void**)&dDEGI, g_DEGI);
    cudaGetSymbolAddress((void**)&dOFF,  g_OFF);
    cudaGetSymbolAddress((void**)&dCUR,  g_CUR);
    cudaGetSymbolAddress((void**)&dCSR,  g_CSR);
    cudaGetSymbolAddress((void**)&dBSUM, g_BSUM);

    const size_t smemC = 4 * A_BYTES + 4 * B_BYTES;   // 110,592 B
    cudaFuncSetAttribute(combine_kernel<true>,
                         cudaFuncAttributeMaxDynamicSharedMemorySize, (int)smemC);
    cudaFuncSetAttribute(combine_kernel<false>,
                         cudaFuncAttributeMaxDynamicSharedMemorySize, (int)smemC);

    const int gridC = (NN + RPB - 1) / RPB;   // 2188
    const int gridG = (NN * 32 + 255) / 256;  // warp per row
    const int gridI = (NN + 3) / 4;           // init+hist (covers NE too)

    // ---- prologue: features + CSR ----
    cudaMemsetAsync(dDEGI, 0, NN * sizeof(int));
    init_hist_kernel<<<gridI, 256>>>(ei, dDEGI, movie_x, user_emb,
                                     movie_emb, lin_W, lin_b, dX);          // #1
    scanA_kernel<<<NB2, 256>>>(dDEGI, dBSUM);                               // #2
    scanB_kernel<<<1, 512>>>(dBSUM, dOFF);                                  // #3
    scanC_kernel<<<NB2, 256>>>(dDEGI, dBSUM, dOFF, dCUR);                   // #4
    fill_kernel<<<(NE + 255) / 256, 256>>>(ei, dCUR, dCSR);                 // #5

    // ---- layer 1 ----
    gather_kernel<<<gridG, 256>>>(dX, dOFF, dCSR, dM);                      // #6
    combine_kernel<true><<<gridC, 256, smemC>>>(dX, dM, W1l, b1, W1r, dY);  // #7

    // ---- layer 2 ----
    gather_kernel<<<gridG, 256>>>(dY, dOFF, dCSR, dM);                      // #8
    combine_kernel<false><<<gridC, 256, smemC>>>(dY, dM, W2l, b2, W2r, dZ); // #9

    // ---- decode ----
    dot_kernel<<<(NEL * 16) / 256, 256>>>(eli, dZ, out);                    // #10
}